// round 14
// baseline (speedup 1.0000x reference)
#include <cuda_runtime.h>
#include <cuda_bf16.h>
#include <cuda_fp16.h>
#include <cstdint>

// ============================================================================
// Problem constants
// ============================================================================
#define IN_F   1024
#define OUT_F  1024
#define INT_DIM 128
#define M_ROWS 16384              // 8 * 2048
#define WN (OUT_F * IN_F)         // 1048576
#define XN (M_ROWS * IN_F)        // 16777216

// Device-global scratch (allocation-free rule: __device__ globals are allowed)
__device__ __half g_W_hi[WN];     // W fp16 high half, [OUT_F][IN_F] K-major
__device__ __half g_W_lo[WN];     // W fp16 low (residual) half
__device__ __half g_x_h[XN];      // x fp16 (single term), [M_ROWS][IN_F]
__device__ float  g_bias[OUT_F];

__device__ __forceinline__ uint32_t smem_u32(const void* p) {
    uint32_t a;
    asm("{ .reg .u64 t; cvta.to.shared.u64 t, %1; cvt.u32.u64 %0, t; }"
        : "=r"(a) : "l"(p));
    return a;
}

__device__ __forceinline__ unsigned pack2h(__half a, __half b) {
    return (unsigned)__half_as_ushort(a) | ((unsigned)__half_as_ushort(b) << 16);
}

// ============================================================================
// Stage 1 (fused prep): one kernel, blockIdx-partitioned.
//   blocks [0, 16384)          : x -> fp16  g_x_h              (64MB rd, 32MB wr)
//   blocks [16384, 17408)      : W = coef @ P_w, fp16 hi+lo    (512MB rd, 4MB wr)
//   blocks [17408, 17412)      : bias = bias_coef @ P_b
// All streaming, DRAM bound (~615 MB -> ~108 us, near HBM ceiling).
// ============================================================================
#define XB (XN / (256 * 4))        // 16384 blocks for x convert
#define WB (WN / (256 * 4))        // 1024 blocks for W materialize

__global__ void __launch_bounds__(256)
prep_kernel(const float* __restrict__ x,  const float* __restrict__ wc,
            const float* __restrict__ bc, const float* __restrict__ Pw,
            const float* __restrict__ Pb) {
    int bx = blockIdx.x;
    int tid = threadIdx.x;

    if (bx < XB) {
        // ---- convert x to fp16 (single term; err <= 2^-11 rel) ----
        size_t pos = ((size_t)bx * 256 + tid) * 4;
        float4 v = *reinterpret_cast<const float4*>(x + pos);
        __half h0 = __float2half_rn(v.x), h1 = __float2half_rn(v.y);
        __half h2 = __float2half_rn(v.z), h3 = __float2half_rn(v.w);
        *reinterpret_cast<uint2*>(g_x_h + pos) =
            make_uint2(pack2h(h0, h1), pack2h(h2, h3));
    } else if (bx < XB + WB) {
        // ---- materialize W, split fp16 hi + lo (residual) ----
        __shared__ float c[INT_DIM];
        if (tid < INT_DIM) c[tid] = wc[tid];
        __syncthreads();
        size_t pos = ((size_t)(bx - XB) * 256 + tid) * 4;
        float4 acc = make_float4(0.f, 0.f, 0.f, 0.f);
#pragma unroll 8
        for (int d = 0; d < INT_DIM; d++) {
            float4 p = *reinterpret_cast<const float4*>(Pw + (size_t)d * WN + pos);
            float cd = c[d];
            acc.x = fmaf(cd, p.x, acc.x);
            acc.y = fmaf(cd, p.y, acc.y);
            acc.z = fmaf(cd, p.z, acc.z);
            acc.w = fmaf(cd, p.w, acc.w);
        }
        __half h0 = __float2half_rn(acc.x), h1 = __float2half_rn(acc.y);
        __half h2 = __float2half_rn(acc.z), h3 = __float2half_rn(acc.w);
        __half l0 = __float2half_rn(acc.x - __half2float(h0));
        __half l1 = __float2half_rn(acc.y - __half2float(h1));
        __half l2 = __float2half_rn(acc.z - __half2float(h2));
        __half l3 = __float2half_rn(acc.w - __half2float(h3));
        *reinterpret_cast<uint2*>(g_W_hi + pos) = make_uint2(pack2h(h0, h1), pack2h(h2, h3));
        *reinterpret_cast<uint2*>(g_W_lo + pos) = make_uint2(pack2h(l0, l1), pack2h(l2, l3));
    } else {
        // ---- materialize bias ----
        __shared__ float c[INT_DIM];
        if (tid < INT_DIM) c[tid] = bc[tid];
        __syncthreads();
        int o = (bx - XB - WB) * 256 + tid;
        float acc = 0.f;
#pragma unroll 8
        for (int d = 0; d < INT_DIM; d++)
            acc = fmaf(c[d], Pb[(size_t)d * OUT_F + o], acc);
        g_bias[o] = acc;
    }
}

// ============================================================================
// Stage 2: fp16-split GEMM via mma.sync.m16n8k16.f32.f16.f16.f32.
//   acc += x_h*W_hi + x_h*W_lo        (2 MMAs per k16, vs 3 for bf16 split;
//   x fp16 rounding -> rel err ~2-3e-4, threshold 1e-3)
//
// CTA tile 128(M) x 64(N), 4 warps 2(M) x 2(N), warp tile 64x32, K-chunk 64.
// Stage = [A 16K | B_hi 8K | B_lo 8K] = 32 KB, double-buffered 64 KB/CTA
// -> THREE independent CTAs per SM (192 KB smem, 12 warps = 3/SMSP), on top
// of round 12's 2-CTA win (tensor 72.6 -> 76.1%).
// 16B chunk ch of row r stored at ch ^ (r & 7) -> conflict-free ldmatrix.
// ============================================================================
#define SM_STAGE 32768
#define OFF_A    0
#define OFF_B_HI 16384
#define OFF_B_LO 24576
#define GEMM_SMEM (2 * SM_STAGE)
#define NKC 16   // 1024 / 64

__device__ __forceinline__ void ldsm_x4(uint32_t* r, uint32_t addr) {
    asm volatile("ldmatrix.sync.aligned.m8n8.x4.shared.b16 {%0,%1,%2,%3}, [%4];"
                 : "=r"(r[0]), "=r"(r[1]), "=r"(r[2]), "=r"(r[3]) : "r"(addr));
}
__device__ __forceinline__ void mma_f16(float* d, const uint32_t* a, const uint32_t* b) {
    asm volatile(
        "mma.sync.aligned.m16n8k16.row.col.f32.f16.f16.f32 "
        "{%0,%1,%2,%3}, {%4,%5,%6,%7}, {%8,%9}, {%0,%1,%2,%3};"
        : "+f"(d[0]), "+f"(d[1]), "+f"(d[2]), "+f"(d[3])
        : "r"(a[0]), "r"(a[1]), "r"(a[2]), "r"(a[3]), "r"(b[0]), "r"(b[1]));
}
__device__ __forceinline__ void cp_async16(uint32_t dst, const void* src) {
    asm volatile("cp.async.cg.shared.global [%0], [%1], 16;"
                 :: "r"(dst), "l"(src) : "memory");
}
#define CP_COMMIT() asm volatile("cp.async.commit_group;" ::: "memory")
#define CP_WAIT0()  asm volatile("cp.async.wait_group 0;" ::: "memory")

// swizzled byte offset inside one [rows x 128B] tile
__device__ __forceinline__ uint32_t sw_off(int row, int ch16) {
    return (uint32_t)(row * 128 + ((ch16 ^ (row & 7)) << 4));
}

__global__ void __launch_bounds__(128, 3)
gemm_kernel(float* __restrict__ out) {
    extern __shared__ char smem[];
    uint32_t sb = smem_u32(smem);
    int tid  = threadIdx.x;
    int wid  = tid >> 5;          // 0..3
    int lane = tid & 31;
    int wm   = wid >> 1;          // 0..1, 64-row half of M128
    int wn   = wid & 1;           // 0..1, 32-col half of N64
    // Consecutive blocks share the same x m-tile -> L2 reuse of x.
    int m0 = (int)(blockIdx.x >> 4) * 128;
    int n0 = (int)(blockIdx.x & 15) * 64;

    const __half* ahp = g_x_h  + (size_t)m0 * IN_F;
    const __half* bhp = g_W_hi + (size_t)n0 * IN_F;
    const __half* blp = g_W_lo + (size_t)n0 * IN_F;

    // cp.async geometry (128 threads):
    // A: 128 rows x 8 ch = 1024 slots, 8 per thread
    // B halves: 64 rows x 8 ch = 512 slots, 4 per thread each
    int ar[8], ach[8];
#pragma unroll
    for (int j = 0; j < 8; ++j) { int e = tid + j * 128; ar[j] = e >> 3; ach[j] = e & 7; }
    int br[4], bch[4];
#pragma unroll
    for (int j = 0; j < 4; ++j) { int e = tid + j * 128; br[j] = e >> 3; bch[j] = e & 7; }

    float acc[4][4][4];
#pragma unroll
    for (int mi = 0; mi < 4; ++mi)
#pragma unroll
        for (int ni = 0; ni < 4; ++ni)
#pragma unroll
            for (int q = 0; q < 4; ++q) acc[mi][ni][q] = 0.f;

#define LOAD_CHUNK(kc, stage_off) do {                                         \
        int _k = (kc) * 64;                                                    \
        uint32_t _s = sb + (stage_off);                                        \
        _Pragma("unroll")                                                      \
        for (int j = 0; j < 8; ++j) {                                          \
            uint32_t d = sw_off(ar[j], ach[j]);                                \
            size_t g = (size_t)ar[j] * IN_F + _k + ach[j] * 8;                 \
            cp_async16(_s + OFF_A + d, ahp + g);                               \
        }                                                                      \
        _Pragma("unroll")                                                      \
        for (int j = 0; j < 4; ++j) {                                          \
            uint32_t d = sw_off(br[j], bch[j]);                                \
            size_t g = (size_t)br[j] * IN_F + _k + bch[j] * 8;                 \
            cp_async16(_s + OFF_B_HI + d, bhp + g);                            \
            cp_async16(_s + OFF_B_LO + d, blp + g);                            \
        }                                                                      \
        CP_COMMIT();                                                           \
    } while (0)

    // ---- prologue: fill buffer 0 with chunk 0 ----
    LOAD_CHUNK(0, 0);
    CP_WAIT0();
    __syncthreads();

    // ---- main loop over 16 K-chunks, double-buffered ----
    for (int c = 0; c < NKC; ++c) {
        uint32_t buf  = (uint32_t)(c & 1) * SM_STAGE;
        uint32_t nbuf = buf ^ SM_STAGE;
        bool pf = (c + 1 < NKC);

        if (pf) LOAD_CHUNK(c + 1, nbuf);

        // ---- compute on buf: 4 k16 steps ----
#pragma unroll
        for (int ks = 0; ks < 4; ++ks) {
            // B fragments: 2 x ldmatrix.x4 per half (paired n8 groups)
            uint32_t bhi[4][2], blo[4][2];
#pragma unroll
            for (int nip = 0; nip < 2; ++nip) {
                int nrow = wn * 32 + nip * 16 + ((lane >> 4) << 3) + (lane & 7);
                int ch   = ks * 2 + ((lane >> 3) & 1);
                uint32_t a = sb + buf + sw_off(nrow, ch);
                ldsm_x4(&bhi[nip * 2][0], a + OFF_B_HI);
                ldsm_x4(&blo[nip * 2][0], a + OFF_B_LO);
            }
            // A fragments
            uint32_t af[4][4];
#pragma unroll
            for (int mi = 0; mi < 4; ++mi) {
                int mrow = wm * 64 + mi * 16 + (lane & 15);
                int ch   = ks * 2 + (lane >> 4);
                uint32_t a = sb + buf + sw_off(mrow, ch);
                ldsm_x4(af[mi], a + OFF_A);
            }
            // 32 MMAs grouped by term: same-acc RAW chains 16 apart
#pragma unroll
            for (int mi = 0; mi < 4; ++mi)
#pragma unroll
                for (int ni = 0; ni < 4; ++ni)
                    mma_f16(acc[mi][ni], af[mi], bhi[ni]);
#pragma unroll
            for (int mi = 0; mi < 4; ++mi)
#pragma unroll
                for (int ni = 0; ni < 4; ++ni)
                    mma_f16(acc[mi][ni], af[mi], blo[ni]);
        }

        if (pf) {
            CP_WAIT0();
            __syncthreads();
        }
    }
#undef LOAD_CHUNK

    // ---- epilogue: acc -> global with bias ----
#pragma unroll
    for (int ni = 0; ni < 4; ++ni) {
        int col = n0 + wn * 32 + ni * 8 + ((lane & 3) << 1);
        float b0 = g_bias[col];
        float b1 = g_bias[col + 1];
#pragma unroll
        for (int mi = 0; mi < 4; ++mi) {
            int row0 = m0 + wm * 64 + mi * 16 + (lane >> 2);
            float2 v0 = make_float2(acc[mi][ni][0] + b0, acc[mi][ni][1] + b1);
            float2 v1 = make_float2(acc[mi][ni][2] + b0, acc[mi][ni][3] + b1);
            *reinterpret_cast<float2*>(out + (size_t)row0 * OUT_F + col) = v0;
            *reinterpret_cast<float2*>(out + (size_t)(row0 + 8) * OUT_F + col) = v1;
        }
    }
}

// ============================================================================
// kernel_launch: 2 graph-capturable kernel launches, no sync, no alloc.
// Inputs (metadata order): x, weight_coef, bias_coef, P_w, P_b. Output fp32.
// ============================================================================
extern "C" void kernel_launch(void* const* d_in, const int* in_sizes, int n_in,
                              void* d_out, int out_size) {
    const float* x  = (const float*)d_in[0];
    const float* wc = (const float*)d_in[1];
    const float* bc = (const float*)d_in[2];
    const float* Pw = (const float*)d_in[3];
    const float* Pb = (const float*)d_in[4];
    float* out = (float*)d_out;

    (void)in_sizes; (void)n_in; (void)out_size;

    cudaFuncSetAttribute(gemm_kernel,
                         cudaFuncAttributeMaxDynamicSharedMemorySize, GEMM_SMEM);

    // Stage 1: fused prep (x fp16 + W fp16 hi/lo + bias), DRAM bound ~615MB
    prep_kernel<<<XB + WB + OUT_F / 256, 256>>>(x, wc, bc, Pw, Pb);

    // Stage 2: y = x @ W^T + b via fp16-split mma.sync (2 MMAs per k16 step)
    // Grid: 128 M-tiles x 16 N-tiles; same-m-tile blocks adjacent for x reuse.
    // 128-thread CTAs, 64 KB smem -> 3 independent CTAs per SM.
    gemm_kernel<<<(M_ROWS / 128) * (OUT_F / 64), 128, GEMM_SMEM>>>(out);
}

// round 15
// speedup vs baseline: 1.0013x; 1.0013x over previous
#include <cuda_runtime.h>
#include <cuda_bf16.h>
#include <cuda_fp16.h>
#include <cstdint>

// ============================================================================
// Problem constants
// ============================================================================
#define IN_F   1024
#define OUT_F  1024
#define INT_DIM 128
#define M_ROWS 16384              // 8 * 2048
#define WN (OUT_F * IN_F)         // 1048576
#define XN (M_ROWS * IN_F)        // 16777216

// Device-global scratch (allocation-free rule: __device__ globals are allowed)
__device__ __half g_W_hi[WN];     // W fp16 high half, [OUT_F][IN_F] K-major
__device__ __half g_W_lo[WN];     // W fp16 low (residual) half
__device__ __half g_x_h[XN];      // x fp16 (single term), [M_ROWS][IN_F]
__device__ float  g_bias[OUT_F];

__device__ __forceinline__ uint32_t smem_u32(const void* p) {
    uint32_t a;
    asm("{ .reg .u64 t; cvta.to.shared.u64 t, %1; cvt.u32.u64 %0, t; }"
        : "=r"(a) : "l"(p));
    return a;
}

__device__ __forceinline__ unsigned pack2h(__half a, __half b) {
    return (unsigned)__half_as_ushort(a) | ((unsigned)__half_as_ushort(b) << 16);
}

// ============================================================================
// Stage 1 (fused prep): one kernel, blockIdx-partitioned.
//   blocks [0, 16384)          : x -> fp16  g_x_h              (64MB rd, 32MB wr)
//   blocks [16384, 17408)      : W = coef @ P_w, fp16 hi+lo    (512MB rd, 4MB wr)
//   blocks [17408, 17412)      : bias = bias_coef @ P_b
// All streaming, DRAM bound (~615 MB -> ~108 us, near HBM ceiling).
// ============================================================================
#define XB (XN / (256 * 4))        // 16384 blocks for x convert
#define WB (WN / (256 * 4))        // 1024 blocks for W materialize

__global__ void __launch_bounds__(256)
prep_kernel(const float* __restrict__ x,  const float* __restrict__ wc,
            const float* __restrict__ bc, const float* __restrict__ Pw,
            const float* __restrict__ Pb) {
    int bx = blockIdx.x;
    int tid = threadIdx.x;

    if (bx < XB) {
        // ---- convert x to fp16 (single term; err <= 2^-11 rel) ----
        size_t pos = ((size_t)bx * 256 + tid) * 4;
        float4 v = *reinterpret_cast<const float4*>(x + pos);
        __half h0 = __float2half_rn(v.x), h1 = __float2half_rn(v.y);
        __half h2 = __float2half_rn(v.z), h3 = __float2half_rn(v.w);
        *reinterpret_cast<uint2*>(g_x_h + pos) =
            make_uint2(pack2h(h0, h1), pack2h(h2, h3));
    } else if (bx < XB + WB) {
        // ---- materialize W, split fp16 hi + lo (residual) ----
        __shared__ float c[INT_DIM];
        if (tid < INT_DIM) c[tid] = wc[tid];
        __syncthreads();
        size_t pos = ((size_t)(bx - XB) * 256 + tid) * 4;
        float4 acc = make_float4(0.f, 0.f, 0.f, 0.f);
#pragma unroll 8
        for (int d = 0; d < INT_DIM; d++) {
            float4 p = *reinterpret_cast<const float4*>(Pw + (size_t)d * WN + pos);
            float cd = c[d];
            acc.x = fmaf(cd, p.x, acc.x);
            acc.y = fmaf(cd, p.y, acc.y);
            acc.z = fmaf(cd, p.z, acc.z);
            acc.w = fmaf(cd, p.w, acc.w);
        }
        __half h0 = __float2half_rn(acc.x), h1 = __float2half_rn(acc.y);
        __half h2 = __float2half_rn(acc.z), h3 = __float2half_rn(acc.w);
        __half l0 = __float2half_rn(acc.x - __half2float(h0));
        __half l1 = __float2half_rn(acc.y - __half2float(h1));
        __half l2 = __float2half_rn(acc.z - __half2float(h2));
        __half l3 = __float2half_rn(acc.w - __half2float(h3));
        *reinterpret_cast<uint2*>(g_W_hi + pos) = make_uint2(pack2h(h0, h1), pack2h(h2, h3));
        *reinterpret_cast<uint2*>(g_W_lo + pos) = make_uint2(pack2h(l0, l1), pack2h(l2, l3));
    } else {
        // ---- materialize bias ----
        __shared__ float c[INT_DIM];
        if (tid < INT_DIM) c[tid] = bc[tid];
        __syncthreads();
        int o = (bx - XB - WB) * 256 + tid;
        float acc = 0.f;
#pragma unroll 8
        for (int d = 0; d < INT_DIM; d++)
            acc = fmaf(c[d], Pb[(size_t)d * OUT_F + o], acc);
        g_bias[o] = acc;
    }
}

// ============================================================================
// Stage 2: fp16-split GEMM via mma.sync.m16n8k16.f32.f16.f16.f32.
//   acc += x_h*W_hi + x_h*W_lo        (2 MMAs per k16, vs 3 for bf16 split;
//   x fp16 rounding -> rel err ~2-3e-4, threshold 1e-3)
//
// CTA tile 128(M) x 64(N), 4 warps 2(M) x 2(N), warp tile 64x32, K-chunk 64.
// Stage = [A 16K | B_hi 8K | B_lo 8K] = 32 KB, double-buffered 64 KB/CTA
// -> THREE independent CTAs per SM (192 KB smem, 12 warps = 3/SMSP), on top
// of round 12's 2-CTA win (tensor 72.6 -> 76.1%).
// 16B chunk ch of row r stored at ch ^ (r & 7) -> conflict-free ldmatrix.
// ============================================================================
#define SM_STAGE 32768
#define OFF_A    0
#define OFF_B_HI 16384
#define OFF_B_LO 24576
#define GEMM_SMEM (2 * SM_STAGE)
#define NKC 16   // 1024 / 64

__device__ __forceinline__ void ldsm_x4(uint32_t* r, uint32_t addr) {
    asm volatile("ldmatrix.sync.aligned.m8n8.x4.shared.b16 {%0,%1,%2,%3}, [%4];"
                 : "=r"(r[0]), "=r"(r[1]), "=r"(r[2]), "=r"(r[3]) : "r"(addr));
}
__device__ __forceinline__ void mma_f16(float* d, const uint32_t* a, const uint32_t* b) {
    asm volatile(
        "mma.sync.aligned.m16n8k16.row.col.f32.f16.f16.f32 "
        "{%0,%1,%2,%3}, {%4,%5,%6,%7}, {%8,%9}, {%0,%1,%2,%3};"
        : "+f"(d[0]), "+f"(d[1]), "+f"(d[2]), "+f"(d[3])
        : "r"(a[0]), "r"(a[1]), "r"(a[2]), "r"(a[3]), "r"(b[0]), "r"(b[1]));
}
__device__ __forceinline__ void cp_async16(uint32_t dst, const void* src) {
    asm volatile("cp.async.cg.shared.global [%0], [%1], 16;"
                 :: "r"(dst), "l"(src) : "memory");
}
#define CP_COMMIT() asm volatile("cp.async.commit_group;" ::: "memory")
#define CP_WAIT0()  asm volatile("cp.async.wait_group 0;" ::: "memory")

// swizzled byte offset inside one [rows x 128B] tile
__device__ __forceinline__ uint32_t sw_off(int row, int ch16) {
    return (uint32_t)(row * 128 + ((ch16 ^ (row & 7)) << 4));
}

__global__ void __launch_bounds__(128, 3)
gemm_kernel(float* __restrict__ out) {
    extern __shared__ char smem[];
    uint32_t sb = smem_u32(smem);
    int tid  = threadIdx.x;
    int wid  = tid >> 5;          // 0..3
    int lane = tid & 31;
    int wm   = wid >> 1;          // 0..1, 64-row half of M128
    int wn   = wid & 1;           // 0..1, 32-col half of N64
    // Consecutive blocks share the same x m-tile -> L2 reuse of x.
    int m0 = (int)(blockIdx.x >> 4) * 128;
    int n0 = (int)(blockIdx.x & 15) * 64;

    const __half* ahp = g_x_h  + (size_t)m0 * IN_F;
    const __half* bhp = g_W_hi + (size_t)n0 * IN_F;
    const __half* blp = g_W_lo + (size_t)n0 * IN_F;

    // cp.async geometry (128 threads):
    // A: 128 rows x 8 ch = 1024 slots, 8 per thread
    // B halves: 64 rows x 8 ch = 512 slots, 4 per thread each
    int ar[8], ach[8];
#pragma unroll
    for (int j = 0; j < 8; ++j) { int e = tid + j * 128; ar[j] = e >> 3; ach[j] = e & 7; }
    int br[4], bch[4];
#pragma unroll
    for (int j = 0; j < 4; ++j) { int e = tid + j * 128; br[j] = e >> 3; bch[j] = e & 7; }

    float acc[4][4][4];
#pragma unroll
    for (int mi = 0; mi < 4; ++mi)
#pragma unroll
        for (int ni = 0; ni < 4; ++ni)
#pragma unroll
            for (int q = 0; q < 4; ++q) acc[mi][ni][q] = 0.f;

#define LOAD_CHUNK(kc, stage_off) do {                                         \
        int _k = (kc) * 64;                                                    \
        uint32_t _s = sb + (stage_off);                                        \
        _Pragma("unroll")                                                      \
        for (int j = 0; j < 8; ++j) {                                          \
            uint32_t d = sw_off(ar[j], ach[j]);                                \
            size_t g = (size_t)ar[j] * IN_F + _k + ach[j] * 8;                 \
            cp_async16(_s + OFF_A + d, ahp + g);                               \
        }                                                                      \
        _Pragma("unroll")                                                      \
        for (int j = 0; j < 4; ++j) {                                          \
            uint32_t d = sw_off(br[j], bch[j]);                                \
            size_t g = (size_t)br[j] * IN_F + _k + bch[j] * 8;                 \
            cp_async16(_s + OFF_B_HI + d, bhp + g);                            \
            cp_async16(_s + OFF_B_LO + d, blp + g);                            \
        }                                                                      \
        CP_COMMIT();                                                           \
    } while (0)

    // ---- prologue: fill buffer 0 with chunk 0 ----
    LOAD_CHUNK(0, 0);
    CP_WAIT0();
    __syncthreads();

    // ---- main loop over 16 K-chunks, double-buffered ----
    for (int c = 0; c < NKC; ++c) {
        uint32_t buf  = (uint32_t)(c & 1) * SM_STAGE;
        uint32_t nbuf = buf ^ SM_STAGE;
        bool pf = (c + 1 < NKC);

        if (pf) LOAD_CHUNK(c + 1, nbuf);

        // ---- compute on buf: 4 k16 steps ----
#pragma unroll
        for (int ks = 0; ks < 4; ++ks) {
            // B fragments: 2 x ldmatrix.x4 per half (paired n8 groups)
            uint32_t bhi[4][2], blo[4][2];
#pragma unroll
            for (int nip = 0; nip < 2; ++nip) {
                int nrow = wn * 32 + nip * 16 + ((lane >> 4) << 3) + (lane & 7);
                int ch   = ks * 2 + ((lane >> 3) & 1);
                uint32_t a = sb + buf + sw_off(nrow, ch);
                ldsm_x4(&bhi[nip * 2][0], a + OFF_B_HI);
                ldsm_x4(&blo[nip * 2][0], a + OFF_B_LO);
            }
            // A fragments
            uint32_t af[4][4];
#pragma unroll
            for (int mi = 0; mi < 4; ++mi) {
                int mrow = wm * 64 + mi * 16 + (lane & 15);
                int ch   = ks * 2 + (lane >> 4);
                uint32_t a = sb + buf + sw_off(mrow, ch);
                ldsm_x4(af[mi], a + OFF_A);
            }
            // 32 MMAs grouped by term: same-acc RAW chains 16 apart
#pragma unroll
            for (int mi = 0; mi < 4; ++mi)
#pragma unroll
                for (int ni = 0; ni < 4; ++ni)
                    mma_f16(acc[mi][ni], af[mi], bhi[ni]);
#pragma unroll
            for (int mi = 0; mi < 4; ++mi)
#pragma unroll
                for (int ni = 0; ni < 4; ++ni)
                    mma_f16(acc[mi][ni], af[mi], blo[ni]);
        }

        if (pf) {
            CP_WAIT0();
            __syncthreads();
        }
    }
#undef LOAD_CHUNK

    // ---- epilogue: acc -> global with bias ----
#pragma unroll
    for (int ni = 0; ni < 4; ++ni) {
        int col = n0 + wn * 32 + ni * 8 + ((lane & 3) << 1);
        float b0 = g_bias[col];
        float b1 = g_bias[col + 1];
#pragma unroll
        for (int mi = 0; mi < 4; ++mi) {
            int row0 = m0 + wm * 64 + mi * 16 + (lane >> 2);
            float2 v0 = make_float2(acc[mi][ni][0] + b0, acc[mi][ni][1] + b1);
            float2 v1 = make_float2(acc[mi][ni][2] + b0, acc[mi][ni][3] + b1);
            *reinterpret_cast<float2*>(out + (size_t)row0 * OUT_F + col) = v0;
            *reinterpret_cast<float2*>(out + (size_t)(row0 + 8) * OUT_F + col) = v1;
        }
    }
}

// ============================================================================
// kernel_launch: 2 graph-capturable kernel launches, no sync, no alloc.
// Inputs (metadata order): x, weight_coef, bias_coef, P_w, P_b. Output fp32.
// ============================================================================
extern "C" void kernel_launch(void* const* d_in, const int* in_sizes, int n_in,
                              void* d_out, int out_size) {
    const float* x  = (const float*)d_in[0];
    const float* wc = (const float*)d_in[1];
    const float* bc = (const float*)d_in[2];
    const float* Pw = (const float*)d_in[3];
    const float* Pb = (const float*)d_in[4];
    float* out = (float*)d_out;

    (void)in_sizes; (void)n_in; (void)out_size;

    cudaFuncSetAttribute(gemm_kernel,
                         cudaFuncAttributeMaxDynamicSharedMemorySize, GEMM_SMEM);

    // Stage 1: fused prep (x fp16 + W fp16 hi/lo + bias), DRAM bound ~615MB
    prep_kernel<<<XB + WB + OUT_F / 256, 256>>>(x, wc, bc, Pw, Pb);

    // Stage 2: y = x @ W^T + b via fp16-split mma.sync (2 MMAs per k16 step)
    // Grid: 128 M-tiles x 16 N-tiles; same-m-tile blocks adjacent for x reuse.
    // 128-thread CTAs, 64 KB smem -> 3 independent CTAs per SM.
    gemm_kernel<<<(M_ROWS / 128) * (OUT_F / 64), 128, GEMM_SMEM>>>(out);
}